// round 8
// baseline (speedup 1.0000x reference)
#include <cuda_runtime.h>
#include <cstdint>

// RelationalKENN on GB300.
// Phase A: u = unary + unary_enhance(unary)         (100K x 16)
// Phase B: per-edge 3-literal softmax clauses, bp = binary + db,
//          up scatter-added via red.global.add.v4.f32.
//
// R7: edge kernel body is the R1 best (one edge/thread, 32 regs, LSU-floor
// organization). New: PDL overlap — edge kernel launches programmatically
// while unary runs, front-loads its coalesced input reads (independent of
// unary), then cudaGridDependencySynchronize() before gathers/REDs.

#define MAX_NODES 100000

__device__ float g_u03[MAX_NODES * 4];   // clean copy of u[:,0:4]

static __device__ __forceinline__ void clause2(float xa, float xb,
                                               float sa, float sb, float w,
                                               float &da, float &db) {
    float s0 = xa * sa, s1 = xb * sb;
    float m  = fmaxf(s0, s1);
    float e0 = __expf(s0 - m), e1 = __expf(s1 - m);
    float inv = __fdividef(w, e0 + e1);
    da += sa * e0 * inv;
    db += sb * e1 * inv;
}

static __device__ __forceinline__ void clause3(float xa, float xb, float xc,
                                               float sa, float sb, float sc, float w,
                                               float &da, float &db, float &dc) {
    float s0 = xa * sa, s1 = xb * sb, s2 = xc * sc;
    float m  = fmaxf(fmaxf(s0, s1), s2);
    float e0 = __expf(s0 - m), e1 = __expf(s1 - m), e2 = __expf(s2 - m);
    float inv = __fdividef(w, e0 + e1 + e2);
    da += sa * e0 * inv;
    db += sb * e1 * inv;
    dc += sc * e2 * inv;
}

__global__ void __launch_bounds__(256)
unary_kernel(const float* __restrict__ unary,
             const float* __restrict__ uw,
             float* __restrict__ up,
             int n_nodes) {
    int i = blockIdx.x * blockDim.x + threadIdx.x;
    if (i < n_nodes) {
        const float4* in4 = reinterpret_cast<const float4*>(unary + (size_t)i * 16);
        float x[16];
        {
            float4 t0 = in4[0], t1 = in4[1], t2 = in4[2], t3 = in4[3];
            x[0]=t0.x; x[1]=t0.y; x[2]=t0.z;  x[3]=t0.w;
            x[4]=t1.x; x[5]=t1.y; x[6]=t1.z;  x[7]=t1.w;
            x[8]=t2.x; x[9]=t2.y; x[10]=t2.z; x[11]=t2.w;
            x[12]=t3.x; x[13]=t3.y; x[14]=t3.z; x[15]=t3.w;
        }

        float w0=__ldg(uw+0), w1=__ldg(uw+1), w2=__ldg(uw+2), w3=__ldg(uw+3);
        float w4=__ldg(uw+4), w5=__ldg(uw+5), w6=__ldg(uw+6), w7=__ldg(uw+7);

        float d[16];
#pragma unroll
        for (int k = 0; k < 16; k++) d[k] = 0.0f;

        clause2(x[0],  x[1],          -1.f, 1.f,       w0, d[0],  d[1]);
        clause2(x[1],  x[2],          -1.f, 1.f,       w1, d[1],  d[2]);
        clause3(x[2],  x[3],  x[4],   -1.f, 1.f, 1.f,  w2, d[2],  d[3],  d[4]);
        clause2(x[4],  x[5],          -1.f, 1.f,       w3, d[4],  d[5]);
        clause3(x[6],  x[7],  x[8],   -1.f, 1.f, 1.f,  w4, d[6],  d[7],  d[8]);
        clause2(x[8],  x[9],          -1.f, 1.f,       w5, d[8],  d[9]);
        clause3(x[10], x[11], x[12],  -1.f, 1.f, 1.f,  w6, d[10], d[11], d[12]);
        clause3(x[13], x[14], x[15],  -1.f, 1.f, 1.f,  w7, d[13], d[14], d[15]);

        float u[16];
#pragma unroll
        for (int k = 0; k < 16; k++) u[k] = x[k] + d[k];

        float4* out4 = reinterpret_cast<float4*>(up + (size_t)i * 16);
        out4[0] = make_float4(u[0],  u[1],  u[2],  u[3]);
        out4[1] = make_float4(u[4],  u[5],  u[6],  u[7]);
        out4[2] = make_float4(u[8],  u[9],  u[10], u[11]);
        out4[3] = make_float4(u[12], u[13], u[14], u[15]);

        reinterpret_cast<float4*>(g_u03)[i] = make_float4(u[0], u[1], u[2], u[3]);
    }

    // Allow the dependent edge kernel to launch and run its independent
    // preamble while our tail blocks finish.
    cudaTriggerProgrammaticLaunchCompletion();
}

static __device__ __forceinline__ void red_add_v4(float* addr,
                                                  float a, float b, float c, float d) {
    asm volatile("red.global.add.v4.f32 [%0], {%1,%2,%3,%4};"
                 :: "l"(addr), "f"(a), "f"(b), "f"(c), "f"(d)
                 : "memory");
}

__global__ void __launch_bounds__(256)
edge_kernel(const float* __restrict__ binary,
            const int*   __restrict__ index1,
            const int*   __restrict__ index2,
            const float* __restrict__ bw,
            float* __restrict__ up,
            float* __restrict__ bp,
            int n_edges) {
    int e = blockIdx.x * blockDim.x + threadIdx.x;
    if (e >= n_edges) return;

    // ---- independent of the unary kernel: inputs only ----
    int i1 = index1[e];
    int i2 = index2[e];
    float4 b = reinterpret_cast<const float4*>(binary)[e];
    float w0=__ldg(bw+0), w1=__ldg(bw+1), w2=__ldg(bw+2), w3=__ldg(bw+3);

    // ---- wait for unary kernel's g_u03 / up writes to be visible ----
    cudaGridDependencySynchronize();

    float4 a = reinterpret_cast<const float4*>(g_u03)[i1];   // u[index1][0:4]
    float4 c = reinterpret_cast<const float4*>(g_u03)[i2];   // u[index2][0:4]

    float av[4] = {a.x, a.y, a.z, a.w};
    float cv[4] = {c.x, c.y, c.z, c.w};
    float bv[4] = {b.x, b.y, b.z, b.w};
    float wv[4] = {w0, w1, w2, w3};

    float du1[4], du2[4], bpv[4];
#pragma unroll
    for (int i = 0; i < 4; i++) {
        // clause i on joined: idx = [i, 32+i, 16+i], sgn = [-1, -1, +1]
        // sel = [-u1_i, -b_i, +u2_i]
        float s0 = -av[i];
        float s1 = -bv[i];
        float s2 =  cv[i];
        float m  = fmaxf(fmaxf(s0, s1), s2);
        float e0 = __expf(s0 - m);
        float e1 = __expf(s1 - m);
        float e2 = __expf(s2 - m);
        float inv = __fdividef(wv[i], e0 + e1 + e2);
        du1[i] = -e0 * inv;          // scatter into up[index1][i]
        bpv[i] = bv[i] - e1 * inv;   // db_i = -e1*inv
        du2[i] =  e2 * inv;          // scatter into up[index2][i]
    }

    reinterpret_cast<float4*>(bp)[e] = make_float4(bpv[0], bpv[1], bpv[2], bpv[3]);

    red_add_v4(up + (size_t)i1 * 16, du1[0], du1[1], du1[2], du1[3]);
    red_add_v4(up + (size_t)i2 * 16, du2[0], du2[1], du2[2], du2[3]);
}

extern "C" void kernel_launch(void* const* d_in, const int* in_sizes, int n_in,
                              void* d_out, int out_size) {
    const float* unary   = (const float*)d_in[0];
    const float* binary  = (const float*)d_in[1];
    const int*   index1  = (const int*)  d_in[2];
    const int*   index2  = (const int*)  d_in[3];
    const float* uw      = (const float*)d_in[4];
    const float* bw      = (const float*)d_in[5];

    int n_nodes = in_sizes[0] / 16;
    int n_edges = in_sizes[1] / 4;

    float* up = (float*)d_out;
    float* bp = up + (size_t)n_nodes * 16;

    unary_kernel<<<(n_nodes + 255) / 256, 256>>>(unary, uw, up, n_nodes);

    // Edge kernel with programmatic dependent launch: overlaps its launch and
    // independent input reads with the unary kernel's tail.
    cudaLaunchConfig_t cfg = {};
    cfg.gridDim  = dim3((n_edges + 255) / 256, 1, 1);
    cfg.blockDim = dim3(256, 1, 1);
    cfg.dynamicSmemBytes = 0;
    cfg.stream = 0;
    cudaLaunchAttribute attrs[1];
    attrs[0].id = cudaLaunchAttributeProgrammaticStreamSerialization;
    attrs[0].val.programmaticStreamSerializationAllowed = 1;
    cfg.attrs = attrs;
    cfg.numAttrs = 1;
    cudaLaunchKernelEx(&cfg, edge_kernel, binary, index1, index2, bw,
                       up, bp, n_edges);
}

// round 10
// speedup vs baseline: 1.6035x; 1.6035x over previous
#include <cuda_runtime.h>
#include <cstdint>

// RelationalKENN on GB300.
// Phase A: u = unary + unary_enhance(unary)         (100K x 16)
// Phase B: per-edge 3-literal softmax clauses, bp = binary + db,
//          up scatter-added via red.global.add.v4.f32.
//
// R8: revert to the R1 organization (one edge/thread, 32 regs — best measured
// edge time across all rounds). Micro-levers: 128-thread edge blocks for
// smoother occupancy, RED asm without "memory" clobber so ptxas can
// co-schedule the bp store and the two REDs.

#define MAX_NODES 100000

__device__ float g_u03[MAX_NODES * 4];   // clean copy of u[:,0:4]

static __device__ __forceinline__ void clause2(float xa, float xb,
                                               float sa, float sb, float w,
                                               float &da, float &db) {
    float s0 = xa * sa, s1 = xb * sb;
    float m  = fmaxf(s0, s1);
    float e0 = __expf(s0 - m), e1 = __expf(s1 - m);
    float inv = __fdividef(w, e0 + e1);
    da += sa * e0 * inv;
    db += sb * e1 * inv;
}

static __device__ __forceinline__ void clause3(float xa, float xb, float xc,
                                               float sa, float sb, float sc, float w,
                                               float &da, float &db, float &dc) {
    float s0 = xa * sa, s1 = xb * sb, s2 = xc * sc;
    float m  = fmaxf(fmaxf(s0, s1), s2);
    float e0 = __expf(s0 - m), e1 = __expf(s1 - m), e2 = __expf(s2 - m);
    float inv = __fdividef(w, e0 + e1 + e2);
    da += sa * e0 * inv;
    db += sb * e1 * inv;
    dc += sc * e2 * inv;
}

__global__ void __launch_bounds__(256)
unary_kernel(const float* __restrict__ unary,
             const float* __restrict__ uw,
             float* __restrict__ up,
             int n_nodes) {
    int i = blockIdx.x * blockDim.x + threadIdx.x;
    if (i >= n_nodes) return;

    const float4* in4 = reinterpret_cast<const float4*>(unary + (size_t)i * 16);
    float x[16];
    {
        float4 t0 = in4[0], t1 = in4[1], t2 = in4[2], t3 = in4[3];
        x[0]=t0.x; x[1]=t0.y; x[2]=t0.z;  x[3]=t0.w;
        x[4]=t1.x; x[5]=t1.y; x[6]=t1.z;  x[7]=t1.w;
        x[8]=t2.x; x[9]=t2.y; x[10]=t2.z; x[11]=t2.w;
        x[12]=t3.x; x[13]=t3.y; x[14]=t3.z; x[15]=t3.w;
    }

    float w0=__ldg(uw+0), w1=__ldg(uw+1), w2=__ldg(uw+2), w3=__ldg(uw+3);
    float w4=__ldg(uw+4), w5=__ldg(uw+5), w6=__ldg(uw+6), w7=__ldg(uw+7);

    float d[16];
#pragma unroll
    for (int k = 0; k < 16; k++) d[k] = 0.0f;

    clause2(x[0],  x[1],          -1.f, 1.f,       w0, d[0],  d[1]);
    clause2(x[1],  x[2],          -1.f, 1.f,       w1, d[1],  d[2]);
    clause3(x[2],  x[3],  x[4],   -1.f, 1.f, 1.f,  w2, d[2],  d[3],  d[4]);
    clause2(x[4],  x[5],          -1.f, 1.f,       w3, d[4],  d[5]);
    clause3(x[6],  x[7],  x[8],   -1.f, 1.f, 1.f,  w4, d[6],  d[7],  d[8]);
    clause2(x[8],  x[9],          -1.f, 1.f,       w5, d[8],  d[9]);
    clause3(x[10], x[11], x[12],  -1.f, 1.f, 1.f,  w6, d[10], d[11], d[12]);
    clause3(x[13], x[14], x[15],  -1.f, 1.f, 1.f,  w7, d[13], d[14], d[15]);

    float u[16];
#pragma unroll
    for (int k = 0; k < 16; k++) u[k] = x[k] + d[k];

    float4* out4 = reinterpret_cast<float4*>(up + (size_t)i * 16);
    out4[0] = make_float4(u[0],  u[1],  u[2],  u[3]);
    out4[1] = make_float4(u[4],  u[5],  u[6],  u[7]);
    out4[2] = make_float4(u[8],  u[9],  u[10], u[11]);
    out4[3] = make_float4(u[12], u[13], u[14], u[15]);

    reinterpret_cast<float4*>(g_u03)[i] = make_float4(u[0], u[1], u[2], u[3]);
}

// Fire-and-forget vector reduction. No "memory" clobber: up is write-only in
// the edge kernel and disjoint from every read stream, so ptxas may schedule
// it freely against the bp store and subsequent loads. volatile pins it.
static __device__ __forceinline__ void red_add_v4(float* addr,
                                                  float a, float b, float c, float d) {
    asm volatile("red.global.add.v4.f32 [%0], {%1,%2,%3,%4};"
                 :: "l"(addr), "f"(a), "f"(b), "f"(c), "f"(d));
}

__global__ void __launch_bounds__(128)
edge_kernel(const float* __restrict__ binary,
            const int*   __restrict__ index1,
            const int*   __restrict__ index2,
            const float* __restrict__ bw,
            float* __restrict__ up,
            float* __restrict__ bp,
            int n_edges) {
    int e = blockIdx.x * blockDim.x + threadIdx.x;
    if (e >= n_edges) return;

    int i1 = index1[e];
    int i2 = index2[e];

    float4 a = reinterpret_cast<const float4*>(g_u03)[i1];   // u[index1][0:4]
    float4 c = reinterpret_cast<const float4*>(g_u03)[i2];   // u[index2][0:4]
    float4 b = reinterpret_cast<const float4*>(binary)[e];

    float w0=__ldg(bw+0), w1=__ldg(bw+1), w2=__ldg(bw+2), w3=__ldg(bw+3);

    float av[4] = {a.x, a.y, a.z, a.w};
    float cv[4] = {c.x, c.y, c.z, c.w};
    float bv[4] = {b.x, b.y, b.z, b.w};
    float wv[4] = {w0, w1, w2, w3};

    float du1[4], du2[4], bpv[4];
#pragma unroll
    for (int i = 0; i < 4; i++) {
        // clause i on joined: idx = [i, 32+i, 16+i], sgn = [-1, -1, +1]
        // sel = [-u1_i, -b_i, +u2_i]
        float s0 = -av[i];
        float s1 = -bv[i];
        float s2 =  cv[i];
        float m  = fmaxf(fmaxf(s0, s1), s2);
        float e0 = __expf(s0 - m);
        float e1 = __expf(s1 - m);
        float e2 = __expf(s2 - m);
        float inv = __fdividef(wv[i], e0 + e1 + e2);
        du1[i] = -e0 * inv;          // scatter into up[index1][i]
        bpv[i] = bv[i] - e1 * inv;   // db_i = -e1*inv
        du2[i] =  e2 * inv;          // scatter into up[index2][i]
    }

    reinterpret_cast<float4*>(bp)[e] = make_float4(bpv[0], bpv[1], bpv[2], bpv[3]);

    red_add_v4(up + (size_t)i1 * 16, du1[0], du1[1], du1[2], du1[3]);
    red_add_v4(up + (size_t)i2 * 16, du2[0], du2[1], du2[2], du2[3]);
}

extern "C" void kernel_launch(void* const* d_in, const int* in_sizes, int n_in,
                              void* d_out, int out_size) {
    const float* unary   = (const float*)d_in[0];
    const float* binary  = (const float*)d_in[1];
    const int*   index1  = (const int*)  d_in[2];
    const int*   index2  = (const int*)  d_in[3];
    const float* uw      = (const float*)d_in[4];
    const float* bw      = (const float*)d_in[5];

    int n_nodes = in_sizes[0] / 16;
    int n_edges = in_sizes[1] / 4;

    float* up = (float*)d_out;
    float* bp = up + (size_t)n_nodes * 16;

    unary_kernel<<<(n_nodes + 255) / 256, 256>>>(unary, uw, up, n_nodes);
    edge_kernel<<<(n_edges + 127) / 128, 128>>>(binary, index1, index2, bw,
                                                up, bp, n_edges);
}